// round 10
// baseline (speedup 1.0000x reference)
#include <cuda_runtime.h>

#define D_  256
#define N_  32768
#define K_  8192
#define TN  128          // tokens per block
#define TK  256          // codes per block-tile
#define DK  16           // d-depth per smem stage
#define ESP 260          // padded row stride for staged e (floats)
#define SMEM_BYTES ((D_ * TN + 2 * DK * ESP) * (int)sizeof(float))

typedef unsigned long long u64;

__device__ float g_esq[K_];
__device__ int   g_idx[N_];

__device__ __forceinline__ u64 bcast2(float x) {
    u64 r;
    asm("mov.b64 %0, {%1, %1};" : "=l"(r) : "f"(x));
    return r;
}
__device__ __forceinline__ void fma2(u64& d, u64 a, u64 b) {
    asm("fma.rn.f32x2 %0, %1, %2, %0;" : "+l"(d) : "l"(a), "l"(b));
}
__device__ __forceinline__ void unpack2(float& lo, float& hi, u64 v) {
    asm("mov.b64 {%0, %1}, %2;" : "=f"(lo), "=f"(hi) : "l"(v));
}

// ---------------------------------------------------------------------------
// 1) e_sq[k] = ||embeddings[k]||^2 (double accum, float store).
// ---------------------------------------------------------------------------
__global__ void esq_kernel(const float* __restrict__ e) {
    int warp = threadIdx.x >> 5;
    int lane = threadIdx.x & 31;
    int k = blockIdx.x * 8 + warp;
    const float* row = e + (size_t)k * D_;
    double s = 0.0;
#pragma unroll
    for (int j = 0; j < 8; ++j) {
        float v = row[lane + 32 * j];
        s += (double)v * (double)v;
    }
#pragma unroll
    for (int off = 16; off; off >>= 1)
        s += __shfl_xor_sync(0xffffffffu, s, off);
    if (lane == 0) g_esq[k] = (float)s;
}

// ---------------------------------------------------------------------------
// 2) Fused distance-GEMM + argmin using packed fma.rn.f32x2.
//    Block: 128 tokens resident, K in 256-code tiles, double-buffered 16-deep
//    e staging. Thread: 8 tokens x 16 codes (8 strided pairs: k = 2*tx + 32*j).
//    dist = e_sq[k] - 2 * dot(z_n, e_k)
// ---------------------------------------------------------------------------
__global__ void __launch_bounds__(256, 1)
vq_argmin_kernel(const float* __restrict__ z, const float* __restrict__ e) {
    extern __shared__ float sm[];
    float* zs  = sm;              // [D_][TN]
    float* es0 = sm + D_ * TN;    // [2][DK][ESP]

    const int tid = threadIdx.x;
    const int n0  = blockIdx.x * TN;

    // z tile: coalesced float4 along tokens (z is (D, N) row-major).
    for (int i = tid; i < D_ * TN / 4; i += 256) {
        int d = i >> 5;
        int q = i & 31;
        float4 v = *(const float4*)(z + (size_t)d * N_ + n0 + q * 4);
        *(float4*)(zs + d * TN + q * 4) = v;
    }

    const int tx = tid & 15;      // code-group (16 strided pairs -> 16 codes... 8 pairs)
    const int ty = tid >> 4;      // token group (8 tokens)

    // Prologue: stage (k0=0, d0=0) into buffer 0.
    float4 st[4];
#pragma unroll
    for (int r = 0; r < 4; ++r) {
        int i = tid + r * 256;
        int kl = i >> 2, dq = (i & 3) * 4;
        st[r] = *(const float4*)(e + (size_t)kl * D_ + dq);
    }
#pragma unroll
    for (int r = 0; r < 4; ++r) {
        int i = tid + r * 256;
        int kl = i >> 2, dq = (i & 3) * 4;
        es0[(dq + 0) * ESP + kl] = st[r].x;
        es0[(dq + 1) * ESP + kl] = st[r].y;
        es0[(dq + 2) * ESP + kl] = st[r].z;
        es0[(dq + 3) * ESP + kl] = st[r].w;
    }
    __syncthreads();

    float bestd[8];
    int   bestk[8];
#pragma unroll
    for (int i = 0; i < 8; ++i) {
        bestd[i] = __int_as_float(0x7f800000);  // +inf
        bestk[i] = 0;
    }

    const int NSTAGE = (K_ / TK) * (D_ / DK);   // 512
    int buf = 0;

    for (int kt = 0; kt < K_ / TK; ++kt) {
        const int k0 = kt * TK;
        u64 acc[8][8];
#pragma unroll
        for (int i = 0; i < 8; ++i)
#pragma unroll
            for (int j = 0; j < 8; ++j) acc[i][j] = 0ull;

        for (int d0 = 0; d0 < D_; d0 += DK) {
            // Prefetch next stage into registers (hidden under compute).
            int s = kt * (D_ / DK) + (d0 >> 4) + 1;
            bool have = (s < NSTAGE);
            if (have) {
                int nk0 = (s >> 4) * TK;
                int nd0 = (s & 15) * DK;
#pragma unroll
                for (int r = 0; r < 4; ++r) {
                    int i = tid + r * 256;
                    int kl = i >> 2, dq = (i & 3) * 4;
                    st[r] = *(const float4*)(e + (size_t)(nk0 + kl) * D_ + nd0 + dq);
                }
            }

            const float* es = es0 + buf * (DK * ESP);
#pragma unroll
            for (int dd = 0; dd < DK; ++dd) {
                const float* zp = zs + (d0 + dd) * TN + ty * 8;
                const float* ep = es + dd * ESP + 2 * tx;
                // e: 8 strided pairs, conflict-free (16 lanes -> 16 bank-pairs)
                u64 eb[8];
#pragma unroll
                for (int j = 0; j < 8; ++j) eb[j] = *(const u64*)(ep + 32 * j);
                // z: 8 tokens via 2 float4, broadcast-packed
                float4 z0 = *(const float4*)(zp);
                float4 z1 = *(const float4*)(zp + 4);
                float zr[8] = {z0.x, z0.y, z0.z, z0.w, z1.x, z1.y, z1.z, z1.w};
                u64 zb[8];
#pragma unroll
                for (int i = 0; i < 8; ++i) zb[i] = bcast2(zr[i]);
#pragma unroll
                for (int i = 0; i < 8; ++i)
#pragma unroll
                    for (int j = 0; j < 8; ++j)
                        fma2(acc[i][j], zb[i], eb[j]);
            }

            if (have) {
                float* esn = es0 + (buf ^ 1) * (DK * ESP);
#pragma unroll
                for (int r = 0; r < 4; ++r) {
                    int i = tid + r * 256;
                    int kl = i >> 2, dq = (i & 3) * 4;
                    esn[(dq + 0) * ESP + kl] = st[r].x;
                    esn[(dq + 1) * ESP + kl] = st[r].y;
                    esn[(dq + 2) * ESP + kl] = st[r].z;
                    esn[(dq + 3) * ESP + kl] = st[r].w;
                }
            }
            __syncthreads();
            buf ^= 1;
        }

        // Epilogue: dist = e_sq - 2*s, running min (k ascending within thread).
#pragma unroll
        for (int j = 0; j < 8; ++j) {
            int kb = k0 + 2 * tx + 32 * j;
            u64 eq = *(const u64*)(g_esq + kb);
            float eqlo, eqhi;
            unpack2(eqlo, eqhi, eq);
#pragma unroll
            for (int i = 0; i < 8; ++i) {
                float lo, hi;
                unpack2(lo, hi, acc[i][j]);
                float dl = fmaf(-2.0f, lo, eqlo);
                float dh = fmaf(-2.0f, hi, eqhi);
                if (dl < bestd[i]) { bestd[i] = dl; bestk[i] = kb; }
                if (dh < bestd[i]) { bestd[i] = dh; bestk[i] = kb + 1; }
            }
        }
    }

    // Cross-thread argmin over 16 tx lanes, tie -> lower k.
#pragma unroll
    for (int i = 0; i < 8; ++i) {
#pragma unroll
        for (int off = 1; off < 16; off <<= 1) {
            float od = __shfl_xor_sync(0xffffffffu, bestd[i], off);
            int   ok = __shfl_xor_sync(0xffffffffu, bestk[i], off);
            if (od < bestd[i] || (od == bestd[i] && ok < bestk[i])) {
                bestd[i] = od;
                bestk[i] = ok;
            }
        }
        if (tx == 0) g_idx[n0 + ty * 8 + i] = bestk[i];
    }
}

// ---------------------------------------------------------------------------
// 3) Gather z_q[d, n] = embeddings[idx[n], d].
// ---------------------------------------------------------------------------
__global__ void gather_kernel(const float* __restrict__ e,
                              float* __restrict__ out, int write_idx) {
    int tn = threadIdx.x & 31;
    int td = threadIdx.x >> 5;
    int n  = blockIdx.x * 32 + tn;
    int idx = g_idx[n];
    const float* row = e + (size_t)idx * D_ + td * 32;
#pragma unroll
    for (int j = 0; j < 8; ++j) {
        float4 v = *(const float4*)(row + j * 4);
        int d = td * 32 + j * 4;
        out[(size_t)(d + 0) * N_ + n] = v.x;
        out[(size_t)(d + 1) * N_ + n] = v.y;
        out[(size_t)(d + 2) * N_ + n] = v.z;
        out[(size_t)(d + 3) * N_ + n] = v.w;
    }
    if (write_idx && td == 0)
        out[(size_t)D_ * N_ + n] = (float)idx;
}

// ---------------------------------------------------------------------------
extern "C" void kernel_launch(void* const* d_in, const int* in_sizes, int n_in,
                              void* d_out, int out_size) {
    const float* z = (const float*)d_in[0];   // z_e: (256, 32768)
    const float* e = (const float*)d_in[1];   // embeddings: (8192, 256)
    float* out = (float*)d_out;

    cudaFuncSetAttribute(vq_argmin_kernel,
                         cudaFuncAttributeMaxDynamicSharedMemorySize, SMEM_BYTES);

    esq_kernel<<<K_ / 8, 256>>>(e);
    vq_argmin_kernel<<<N_ / TN, 256, SMEM_BYTES>>>(z, e);

    int write_idx = (out_size >= D_ * N_ + N_) ? 1 : 0;
    gather_kernel<<<N_ / 32, 256>>>(e, out, write_idx);
}

// round 11
// speedup vs baseline: 1.0010x; 1.0010x over previous
#include <cuda_runtime.h>

#define D_  256
#define N_  32768
#define K_  8192
#define TN  128          // tokens per block
#define TK  256          // codes per block-tile
#define DK  16           // d-depth per smem stage
#define ESP 260          // padded row stride for staged e (floats)
#define SMEM_BYTES ((D_ * TN + 2 * DK * ESP) * (int)sizeof(float))

typedef unsigned long long u64;

__device__ float g_esq[K_];
__device__ int   g_idx[N_];

__device__ __forceinline__ u64 bcast2(float x) {
    u64 r;
    asm("mov.b64 %0, {%1, %1};" : "=l"(r) : "f"(x));
    return r;
}
__device__ __forceinline__ void fma2(u64& d, u64 a, u64 b) {
    asm("fma.rn.f32x2 %0, %1, %2, %0;" : "+l"(d) : "l"(a), "l"(b));
}
__device__ __forceinline__ void unpack2(float& lo, float& hi, u64 v) {
    asm("mov.b64 {%0, %1}, %2;" : "=f"(lo), "=f"(hi) : "l"(v));
}

// ---------------------------------------------------------------------------
// 1) e_sq[k] = ||embeddings[k]||^2 (double accum, float store).
// ---------------------------------------------------------------------------
__global__ void esq_kernel(const float* __restrict__ e) {
    int warp = threadIdx.x >> 5;
    int lane = threadIdx.x & 31;
    int k = blockIdx.x * 8 + warp;
    const float* row = e + (size_t)k * D_;
    double s = 0.0;
#pragma unroll
    for (int j = 0; j < 8; ++j) {
        float v = row[lane + 32 * j];
        s += (double)v * (double)v;
    }
#pragma unroll
    for (int off = 16; off; off >>= 1)
        s += __shfl_xor_sync(0xffffffffu, s, off);
    if (lane == 0) g_esq[k] = (float)s;
}

// ---------------------------------------------------------------------------
// 2) Fused distance-GEMM + argmin using packed fma.rn.f32x2.
//    Block: 128 tokens resident, K in 256-code tiles, double-buffered 16-deep
//    e staging. Thread: 8 tokens x 16 codes (8 strided pairs: k = 2*tx + 32*j).
//    dist = e_sq[k] - 2 * dot(z_n, e_k)
// ---------------------------------------------------------------------------
__global__ void __launch_bounds__(256, 1)
vq_argmin_kernel(const float* __restrict__ z, const float* __restrict__ e) {
    extern __shared__ float sm[];
    float* zs  = sm;              // [D_][TN]
    float* es0 = sm + D_ * TN;    // [2][DK][ESP]

    const int tid = threadIdx.x;
    const int n0  = blockIdx.x * TN;

    // z tile: coalesced float4 along tokens (z is (D, N) row-major).
    for (int i = tid; i < D_ * TN / 4; i += 256) {
        int d = i >> 5;
        int q = i & 31;
        float4 v = *(const float4*)(z + (size_t)d * N_ + n0 + q * 4);
        *(float4*)(zs + d * TN + q * 4) = v;
    }

    const int tx = tid & 15;      // code-group (16 strided pairs -> 16 codes... 8 pairs)
    const int ty = tid >> 4;      // token group (8 tokens)

    // Prologue: stage (k0=0, d0=0) into buffer 0.
    float4 st[4];
#pragma unroll
    for (int r = 0; r < 4; ++r) {
        int i = tid + r * 256;
        int kl = i >> 2, dq = (i & 3) * 4;
        st[r] = *(const float4*)(e + (size_t)kl * D_ + dq);
    }
#pragma unroll
    for (int r = 0; r < 4; ++r) {
        int i = tid + r * 256;
        int kl = i >> 2, dq = (i & 3) * 4;
        es0[(dq + 0) * ESP + kl] = st[r].x;
        es0[(dq + 1) * ESP + kl] = st[r].y;
        es0[(dq + 2) * ESP + kl] = st[r].z;
        es0[(dq + 3) * ESP + kl] = st[r].w;
    }
    __syncthreads();

    float bestd[8];
    int   bestk[8];
#pragma unroll
    for (int i = 0; i < 8; ++i) {
        bestd[i] = __int_as_float(0x7f800000);  // +inf
        bestk[i] = 0;
    }

    const int NSTAGE = (K_ / TK) * (D_ / DK);   // 512
    int buf = 0;

    for (int kt = 0; kt < K_ / TK; ++kt) {
        const int k0 = kt * TK;
        u64 acc[8][8];
#pragma unroll
        for (int i = 0; i < 8; ++i)
#pragma unroll
            for (int j = 0; j < 8; ++j) acc[i][j] = 0ull;

        for (int d0 = 0; d0 < D_; d0 += DK) {
            // Prefetch next stage into registers (hidden under compute).
            int s = kt * (D_ / DK) + (d0 >> 4) + 1;
            bool have = (s < NSTAGE);
            if (have) {
                int nk0 = (s >> 4) * TK;
                int nd0 = (s & 15) * DK;
#pragma unroll
                for (int r = 0; r < 4; ++r) {
                    int i = tid + r * 256;
                    int kl = i >> 2, dq = (i & 3) * 4;
                    st[r] = *(const float4*)(e + (size_t)(nk0 + kl) * D_ + nd0 + dq);
                }
            }

            const float* es = es0 + buf * (DK * ESP);
#pragma unroll
            for (int dd = 0; dd < DK; ++dd) {
                const float* zp = zs + (d0 + dd) * TN + ty * 8;
                const float* ep = es + dd * ESP + 2 * tx;
                // e: 8 strided pairs, conflict-free (16 lanes -> 16 bank-pairs)
                u64 eb[8];
#pragma unroll
                for (int j = 0; j < 8; ++j) eb[j] = *(const u64*)(ep + 32 * j);
                // z: 8 tokens via 2 float4, broadcast-packed
                float4 z0 = *(const float4*)(zp);
                float4 z1 = *(const float4*)(zp + 4);
                float zr[8] = {z0.x, z0.y, z0.z, z0.w, z1.x, z1.y, z1.z, z1.w};
                u64 zb[8];
#pragma unroll
                for (int i = 0; i < 8; ++i) zb[i] = bcast2(zr[i]);
#pragma unroll
                for (int i = 0; i < 8; ++i)
#pragma unroll
                    for (int j = 0; j < 8; ++j)
                        fma2(acc[i][j], zb[i], eb[j]);
            }

            if (have) {
                float* esn = es0 + (buf ^ 1) * (DK * ESP);
#pragma unroll
                for (int r = 0; r < 4; ++r) {
                    int i = tid + r * 256;
                    int kl = i >> 2, dq = (i & 3) * 4;
                    esn[(dq + 0) * ESP + kl] = st[r].x;
                    esn[(dq + 1) * ESP + kl] = st[r].y;
                    esn[(dq + 2) * ESP + kl] = st[r].z;
                    esn[(dq + 3) * ESP + kl] = st[r].w;
                }
            }
            __syncthreads();
            buf ^= 1;
        }

        // Epilogue: dist = e_sq - 2*s, running min (k ascending within thread).
#pragma unroll
        for (int j = 0; j < 8; ++j) {
            int kb = k0 + 2 * tx + 32 * j;
            u64 eq = *(const u64*)(g_esq + kb);
            float eqlo, eqhi;
            unpack2(eqlo, eqhi, eq);
#pragma unroll
            for (int i = 0; i < 8; ++i) {
                float lo, hi;
                unpack2(lo, hi, acc[i][j]);
                float dl = fmaf(-2.0f, lo, eqlo);
                float dh = fmaf(-2.0f, hi, eqhi);
                if (dl < bestd[i]) { bestd[i] = dl; bestk[i] = kb; }
                if (dh < bestd[i]) { bestd[i] = dh; bestk[i] = kb + 1; }
            }
        }
    }

    // Cross-thread argmin over 16 tx lanes, tie -> lower k.
#pragma unroll
    for (int i = 0; i < 8; ++i) {
#pragma unroll
        for (int off = 1; off < 16; off <<= 1) {
            float od = __shfl_xor_sync(0xffffffffu, bestd[i], off);
            int   ok = __shfl_xor_sync(0xffffffffu, bestk[i], off);
            if (od < bestd[i] || (od == bestd[i] && ok < bestk[i])) {
                bestd[i] = od;
                bestk[i] = ok;
            }
        }
        if (tx == 0) g_idx[n0 + ty * 8 + i] = bestk[i];
    }
}

// ---------------------------------------------------------------------------
// 3) Gather z_q[d, n] = embeddings[idx[n], d].
// ---------------------------------------------------------------------------
__global__ void gather_kernel(const float* __restrict__ e,
                              float* __restrict__ out, int write_idx) {
    int tn = threadIdx.x & 31;
    int td = threadIdx.x >> 5;
    int n  = blockIdx.x * 32 + tn;
    int idx = g_idx[n];
    const float* row = e + (size_t)idx * D_ + td * 32;
#pragma unroll
    for (int j = 0; j < 8; ++j) {
        float4 v = *(const float4*)(row + j * 4);
        int d = td * 32 + j * 4;
        out[(size_t)(d + 0) * N_ + n] = v.x;
        out[(size_t)(d + 1) * N_ + n] = v.y;
        out[(size_t)(d + 2) * N_ + n] = v.z;
        out[(size_t)(d + 3) * N_ + n] = v.w;
    }
    if (write_idx && td == 0)
        out[(size_t)D_ * N_ + n] = (float)idx;
}

// ---------------------------------------------------------------------------
extern "C" void kernel_launch(void* const* d_in, const int* in_sizes, int n_in,
                              void* d_out, int out_size) {
    const float* z = (const float*)d_in[0];   // z_e: (256, 32768)
    const float* e = (const float*)d_in[1];   // embeddings: (8192, 256)
    float* out = (float*)d_out;

    cudaFuncSetAttribute(vq_argmin_kernel,
                         cudaFuncAttributeMaxDynamicSharedMemorySize, SMEM_BYTES);

    esq_kernel<<<K_ / 8, 256>>>(e);
    vq_argmin_kernel<<<N_ / TN, 256, SMEM_BYTES>>>(z, e);

    int write_idx = (out_size >= D_ * N_ + N_) ? 1 : 0;
    gather_kernel<<<N_ / 32, 256>>>(e, out, write_idx);
}